// round 14
// baseline (speedup 1.0000x reference)
#include <cuda_runtime.h>
#include <cstdint>
#include <math.h>

#define T_TOK 4096
#define HDIM  1024
#define IDIM  2048
#define NEXP  8
#define NE    9      // 8 routed + 1 shared pseudo-expert

#define OFF_AUX 4194304
#define OFF_Z   4194305
#define OFF_LOG 4194306

// Scratch: 12288 rows (8192 routed pairs + 4096 shared) x IDIM fp32 activations
__device__ float g_act[12288 * 2048];
__device__ int   g_cnt[NEXP];
__device__ int   g_off[NEXP];
__device__ int   g_tok[NEXP * T_TOK];
__device__ float g_wt[NEXP * T_TOK];
__device__ float g_disp[NEXP];
__device__ float g_prob[NEXP];
__device__ float g_zsum;

// ---------------------------------------------------------------------------
__device__ __forceinline__ float to_tf32(float x) {
    uint32_t u; asm("cvt.rna.tf32.f32 %0, %1;" : "=r"(u) : "f"(x));
    return __uint_as_float(u);
}
__device__ __forceinline__ void cvt4(float4& v) {
    v.x = to_tf32(v.x); v.y = to_tf32(v.y); v.z = to_tf32(v.z); v.w = to_tf32(v.w);
}
// D += A(16x8) * B(8x8), tf32 inputs, f32 accum
__device__ __forceinline__ void mma8(float* d, const uint32_t* a, const uint32_t* b) {
    asm volatile(
        "mma.sync.aligned.m16n8k8.row.col.f32.tf32.tf32.f32 "
        "{%0,%1,%2,%3}, {%4,%5,%6,%7}, {%8,%9}, {%0,%1,%2,%3};"
        : "+f"(d[0]), "+f"(d[1]), "+f"(d[2]), "+f"(d[3])
        : "r"(a[0]), "r"(a[1]), "r"(a[2]), "r"(a[3]), "r"(b[0]), "r"(b[1]));
}
__device__ __forceinline__ uint32_t fb(float x) { return __float_as_uint(x); }

#define LDA  136   // A tile: 32 k-rows x 128 m (padded)
#define LDBG 136   // gateup B tiles: 32 k-rows x 128 n (padded)
#define LDB2 264   // down B tile: 32 k-rows x 256 n (padded)

// ---------------------------------------------------------------------------
__global__ void zero_misc_kernel() {
    int i = threadIdx.x;
    if (i < NEXP) { g_cnt[i] = 0; g_disp[i] = 0.f; g_prob[i] = 0.f; }
    if (i == 0) g_zsum = 0.f;
}

// ---------------------------------------------------------------------------
__global__ void router_kernel(const float* __restrict__ x,
                              const float* __restrict__ rw,
                              float* __restrict__ out) {
    int t = blockIdx.x;
    const float* xr = x + (size_t)t * HDIM;

    float acc[NEXP];
#pragma unroll
    for (int e = 0; e < NEXP; e++) acc[e] = 0.f;

    for (int h = threadIdx.x; h < HDIM; h += 128) {
        float xv = xr[h];
        const float4* w = (const float4*)(rw + (size_t)h * NEXP);
        float4 w0 = w[0], w1 = w[1];
        acc[0] += xv * w0.x; acc[1] += xv * w0.y;
        acc[2] += xv * w0.z; acc[3] += xv * w0.w;
        acc[4] += xv * w1.x; acc[5] += xv * w1.y;
        acc[6] += xv * w1.z; acc[7] += xv * w1.w;
    }

    __shared__ float red[128][NEXP];
    __shared__ float lg[NEXP];
#pragma unroll
    for (int e = 0; e < NEXP; e++) red[threadIdx.x][e] = acc[e];
    __syncthreads();

    if (threadIdx.x < NEXP) {
        float s = 0.f;
        for (int i = 0; i < 128; i++) s += red[i][threadIdx.x];
        lg[threadIdx.x] = s;
    }
    __syncthreads();

    if (threadIdx.x == 0) {
        float mx = lg[0];
#pragma unroll
        for (int e = 1; e < NEXP; e++) mx = fmaxf(mx, lg[e]);
        float p[NEXP]; float sum = 0.f;
#pragma unroll
        for (int e = 0; e < NEXP; e++) { p[e] = expf(lg[e] - mx); sum += p[e]; }
        float lse = mx + logf(sum);
        atomicAdd(&g_zsum, lse * lse);
        float inv = 1.f / sum;

        int i0 = 0; float b0 = -1.f;
#pragma unroll
        for (int e = 0; e < NEXP; e++) {
            p[e] *= inv;
            if (p[e] > b0) { b0 = p[e]; i0 = e; }
            atomicAdd(&g_prob[e], p[e]);
            out[OFF_LOG + (size_t)t * NEXP + e] = lg[e];
        }
        int i1 = -1; float b1 = -1.f;
#pragma unroll
        for (int e = 0; e < NEXP; e++) {
            if (e != i0 && p[e] > b1) { b1 = p[e]; i1 = e; }
        }
        float s2 = b0 + b1;
        float w0 = b0 / s2, w1 = b1 / s2;

        int s0 = atomicAdd(&g_cnt[i0], 1);
        g_tok[i0 * T_TOK + s0] = t; g_wt[i0 * T_TOK + s0] = w0;
        int s1 = atomicAdd(&g_cnt[i1], 1);
        g_tok[i1 * T_TOK + s1] = t; g_wt[i1 * T_TOK + s1] = w1;
        atomicAdd(&g_disp[i0], 0.5f);
        atomicAdd(&g_disp[i1], 0.5f);
    }
}

__global__ void offsets_kernel() {
    int o = 0;
    for (int e = 0; e < NEXP; e++) { g_off[e] = o; o += g_cnt[e]; }
}

// ---------------------------------------------------------------------------
// Pass A: gate/up GEMM via tf32 mma.sync.
// Block tile M=128, N=128 (both matrices), K=32.
// 8 warps: wm = w&1 (64 rows), wn = w>>1 (32 cols). Warp tile 64x32 per matrix.
__global__ __launch_bounds__(256, 1) void gateup_mma_kernel(
    const float* __restrict__ x,
    const float* __restrict__ gate_w, const float* __restrict__ up_w,
    const float* __restrict__ sgate_w, const float* __restrict__ sup_w) {
    int e = blockIdx.z;
    int cnt = (e < NEXP) ? g_cnt[e] : T_TOK;
    int row0 = blockIdx.y * 128;
    if (row0 >= cnt) return;
    int base = (e < NEXP) ? g_off[e] : 2 * T_TOK;
    int n0 = blockIdx.x * 128;
    const float* gw = (e < NEXP) ? gate_w + (size_t)e * HDIM * IDIM : sgate_w;
    const float* uw = (e < NEXP) ? up_w   + (size_t)e * HDIM * IDIM : sup_w;

    extern __shared__ __align__(16) float smem[];
    const int A_SZ = 32 * LDA;           // 4352 floats
    const int B_SZ = 32 * LDBG;          // 4352 floats
    const int STG  = A_SZ + 2 * B_SZ;    // 13056 floats per stage

    __shared__ int s_tok[128];

    int tid = threadIdx.x;
    int w = tid >> 5, lane = tid & 31;
    int g = lane >> 2, tig = lane & 3;
    int wm = w & 1, wn = w >> 1;

    if (tid < 128) {
        int r = row0 + tid;
        s_tok[tid] = (r < cnt) ? ((e < NEXP) ? g_tok[e * T_TOK + r] : r) : -1;
    }
    __syncthreads();

    // staging indices
    int sm = tid >> 1;            // A row 0..127
    int skh = (tid & 1) * 16;     // k half
    const float* arow = x + (size_t)max(s_tok[sm], 0) * HDIM;

    float4 ra[4], rg[4], ru[4];

    auto ldg = [&](int c) {
        int k0 = c * 32;
#pragma unroll
        for (int i = 0; i < 4; i++) {
            ra[i] = *(const float4*)(arow + k0 + skh + i * 4);
            cvt4(ra[i]);
        }
#pragma unroll
        for (int i = 0; i < 4; i++) {
            int q = tid + i * 256;          // 0..1023 float4 ids
            int r = q >> 5, c4 = (q & 31) * 4;
            rg[i] = *(const float4*)(gw + (size_t)(k0 + r) * IDIM + n0 + c4); cvt4(rg[i]);
            ru[i] = *(const float4*)(uw + (size_t)(k0 + r) * IDIM + n0 + c4); cvt4(ru[i]);
        }
    };
    auto sts = [&](int b) {
        float* As = smem + b * STG;
        float* Bg = As + A_SZ;
        float* Bu = Bg + B_SZ;
#pragma unroll
        for (int i = 0; i < 4; i++) {
            As[(skh + i * 4 + 0) * LDA + sm] = ra[i].x;
            As[(skh + i * 4 + 1) * LDA + sm] = ra[i].y;
            As[(skh + i * 4 + 2) * LDA + sm] = ra[i].z;
            As[(skh + i * 4 + 3) * LDA + sm] = ra[i].w;
        }
#pragma unroll
        for (int i = 0; i < 4; i++) {
            int q = tid + i * 256;
            int r = q >> 5, c4 = (q & 31) * 4;
            *(float4*)(Bg + r * LDBG + c4) = rg[i];
            *(float4*)(Bu + r * LDBG + c4) = ru[i];
        }
    };

    float cg[4][4][4], cu[4][4][4];
#pragma unroll
    for (int mi = 0; mi < 4; mi++)
#pragma unroll
        for (int j = 0; j < 4; j++)
#pragma unroll
            for (int q = 0; q < 4; q++) { cg[mi][j][q] = 0.f; cu[mi][j][q] = 0.f; }

    const int NK = HDIM / 32;  // 32
    ldg(0); sts(0); __syncthreads();
    ldg(1);

    for (int c = 0; c < NK; c++) {
        int b = c & 1;
        if (c + 1 < NK) sts(b ^ 1);
        __syncthreads();
        if (c + 2 < NK) ldg(c + 2);

        const float* As = smem + b * STG;
        const float* Bg = As + A_SZ;
        const float* Bu = Bg + B_SZ;
#pragma unroll
        for (int kq = 0; kq < 4; kq++) {
            int kk = kq * 8;
            uint32_t a[4][4];
#pragma unroll
            for (int mi = 0; mi < 4; mi++) {
                int m0 = wm * 64 + mi * 16;
                a[mi][0] = fb(As[(kk + tig) * LDA + m0 + g]);
                a[mi][1] = fb(As[(kk + tig) * LDA + m0 + 8 + g]);
                a[mi][2] = fb(As[(kk + 4 + tig) * LDA + m0 + g]);
                a[mi][3] = fb(As[(kk + 4 + tig) * LDA + m0 + 8 + g]);
            }
            uint32_t bg[4][2], bu[4][2];
#pragma unroll
            for (int j = 0; j < 4; j++) {
                int n = wn * 32 + j * 8 + g;
                bg[j][0] = fb(Bg[(kk + tig) * LDBG + n]);
                bg[j][1] = fb(Bg[(kk + 4 + tig) * LDBG + n]);
                bu[j][0] = fb(Bu[(kk + tig) * LDBG + n]);
                bu[j][1] = fb(Bu[(kk + 4 + tig) * LDBG + n]);
            }
#pragma unroll
            for (int mi = 0; mi < 4; mi++)
#pragma unroll
                for (int j = 0; j < 4; j++) {
                    mma8(cg[mi][j], a[mi], bg[j]);
                    mma8(cu[mi][j], a[mi], bu[j]);
                }
        }
        __syncthreads();
    }

    // Epilogue: silu(gate)*up -> g_act
#pragma unroll
    for (int mi = 0; mi < 4; mi++) {
#pragma unroll
        for (int half = 0; half < 2; half++) {
            int r = wm * 64 + mi * 16 + half * 8 + g;
            if (s_tok[r] < 0) continue;
            float* dst = g_act + (size_t)(base + row0 + r) * IDIM + n0 + wn * 32 + 2 * tig;
#pragma unroll
            for (int j = 0; j < 4; j++) {
                float gv0 = cg[mi][j][half * 2 + 0], uv0 = cu[mi][j][half * 2 + 0];
                float gv1 = cg[mi][j][half * 2 + 1], uv1 = cu[mi][j][half * 2 + 1];
                float2 v;
                v.x = (gv0 / (1.f + __expf(-gv0))) * uv0;
                v.y = (gv1 / (1.f + __expf(-gv1))) * uv1;
                *(float2*)(dst + j * 8) = v;
            }
        }
    }
}

// ---------------------------------------------------------------------------
// Pass B: out[tok] += w * (act_row @ down_w). Block tile M=128, N=256, K=32.
// 8 warps: wm = w&1 (64 rows), wn = w>>1 (64 cols). Warp tile 64x64.
__global__ __launch_bounds__(256, 1) void down_mma_kernel(
    const float* __restrict__ down_w, const float* __restrict__ sdown_w,
    float* __restrict__ out) {
    int e = blockIdx.z;
    int cnt = (e < NEXP) ? g_cnt[e] : T_TOK;
    int row0 = blockIdx.y * 128;
    if (row0 >= cnt) return;
    int base = (e < NEXP) ? g_off[e] : 2 * T_TOK;
    int n0 = blockIdx.x * 256;
    const float* dw = (e < NEXP) ? down_w + (size_t)e * IDIM * HDIM : sdown_w;

    extern __shared__ __align__(16) float smem[];
    const int A_SZ = 32 * LDA;           // 4352
    const int B_SZ = 32 * LDB2;          // 8448
    const int STG  = A_SZ + B_SZ;        // 12800 floats per stage

    __shared__ int   s_tok[128];
    __shared__ float s_w[128];

    int tid = threadIdx.x;
    int w = tid >> 5, lane = tid & 31;
    int g = lane >> 2, tig = lane & 3;
    int wm = w & 1, wn = w >> 1;

    if (tid < 128) {
        int r = row0 + tid;
        if (r < cnt) {
            s_tok[tid] = (e < NEXP) ? g_tok[e * T_TOK + r] : r;
            s_w[tid]   = (e < NEXP) ? g_wt[e * T_TOK + r] : 1.0f;
        } else { s_tok[tid] = -1; s_w[tid] = 0.f; }
    }
    __syncthreads();

    int sm = tid >> 1;
    int skh = (tid & 1) * 16;
    int arow_i = (row0 + sm < cnt) ? (base + row0 + sm) : base;
    const float* arow = g_act + (size_t)arow_i * IDIM;

    float4 ra[4], rb[8];

    auto ldg = [&](int c) {
        int k0 = c * 32;
#pragma unroll
        for (int i = 0; i < 4; i++) {
            ra[i] = *(const float4*)(arow + k0 + skh + i * 4);
            cvt4(ra[i]);
        }
#pragma unroll
        for (int i = 0; i < 8; i++) {
            int q = tid + i * 256;              // 0..2047 float4 ids
            int r = q >> 6, c4 = (q & 63) * 4;
            rb[i] = *(const float4*)(dw + (size_t)(k0 + r) * HDIM + n0 + c4);
            cvt4(rb[i]);
        }
    };
    auto sts = [&](int b) {
        float* As = smem + b * STG;
        float* Bs = As + A_SZ;
#pragma unroll
        for (int i = 0; i < 4; i++) {
            As[(skh + i * 4 + 0) * LDA + sm] = ra[i].x;
            As[(skh + i * 4 + 1) * LDA + sm] = ra[i].y;
            As[(skh + i * 4 + 2) * LDA + sm] = ra[i].z;
            As[(skh + i * 4 + 3) * LDA + sm] = ra[i].w;
        }
#pragma unroll
        for (int i = 0; i < 8; i++) {
            int q = tid + i * 256;
            int r = q >> 6, c4 = (q & 63) * 4;
            *(float4*)(Bs + r * LDB2 + c4) = rb[i];
        }
    };

    float acc[4][8][4];
#pragma unroll
    for (int mi = 0; mi < 4; mi++)
#pragma unroll
        for (int j = 0; j < 8; j++)
#pragma unroll
            for (int q = 0; q < 4; q++) acc[mi][j][q] = 0.f;

    const int NK = IDIM / 32;  // 64
    ldg(0); sts(0); __syncthreads();
    ldg(1);

    for (int c = 0; c < NK; c++) {
        int b = c & 1;
        if (c + 1 < NK) sts(b ^ 1);
        __syncthreads();
        if (c + 2 < NK) ldg(c + 2);

        const float* As = smem + b * STG;
        const float* Bs = As + A_SZ;
#pragma unroll
        for (int kq = 0; kq < 4; kq++) {
            int kk = kq * 8;
            uint32_t a[4][4];
#pragma unroll
            for (int mi = 0; mi < 4; mi++) {
                int m0 = wm * 64 + mi * 16;
                a[mi][0] = fb(As[(kk + tig) * LDA + m0 + g]);
                a[mi][1] = fb(As[(kk + tig) * LDA + m0 + 8 + g]);
                a[mi][2] = fb(As[(kk + 4 + tig) * LDA + m0 + g]);
                a[mi][3] = fb(As[(kk + 4 + tig) * LDA + m0 + 8 + g]);
            }
            uint32_t bf[8][2];
#pragma unroll
            for (int j = 0; j < 8; j++) {
                int n = wn * 64 + j * 8 + g;
                bf[j][0] = fb(Bs[(kk + tig) * LDB2 + n]);
                bf[j][1] = fb(Bs[(kk + 4 + tig) * LDB2 + n]);
            }
#pragma unroll
            for (int mi = 0; mi < 4; mi++)
#pragma unroll
                for (int j = 0; j < 8; j++)
                    mma8(acc[mi][j], a[mi], bf[j]);
        }
        __syncthreads();
    }

    // Epilogue: scale by router weight, atomicAdd into out
#pragma unroll
    for (int mi = 0; mi < 4; mi++) {
#pragma unroll
        for (int half = 0; half < 2; half++) {
            int r = wm * 64 + mi * 16 + half * 8 + g;
            int tok = s_tok[r];
            if (tok < 0) continue;
            float wr = s_w[r];
            float* dst = out + (size_t)tok * HDIM + n0 + wn * 64 + 2 * tig;
#pragma unroll
            for (int j = 0; j < 8; j++) {
                atomicAdd(dst + j * 8 + 0, wr * acc[mi][j][half * 2 + 0]);
                atomicAdd(dst + j * 8 + 1, wr * acc[mi][j][half * 2 + 1]);
            }
        }
    }
}

// ---------------------------------------------------------------------------
__global__ void finalize_kernel(float* __restrict__ out) {
    if (threadIdx.x == 0) {
        float aux = 0.f;
        for (int e = 0; e < NEXP; e++)
            aux += (g_disp[e] / (float)T_TOK) * (g_prob[e] / (float)T_TOK);
        out[OFF_AUX] = (float)NEXP * aux;
        out[OFF_Z]   = g_zsum / (float)T_TOK;
    }
}

// ---------------------------------------------------------------------------
#define SMEM_GATEUP (2 * (32 * LDA + 2 * 32 * LDBG) * 4)  // 104448 B
#define SMEM_DOWN   (2 * (32 * LDA + 32 * LDB2) * 4)      // 102400 B

extern "C" void kernel_launch(void* const* d_in, const int* in_sizes, int n_in,
                              void* d_out, int out_size) {
    const float* x   = (const float*)d_in[0];
    const float* rw  = (const float*)d_in[1];
    const float* gw  = (const float*)d_in[2];
    const float* uw  = (const float*)d_in[3];
    const float* dw  = (const float*)d_in[4];
    const float* sgw = (const float*)d_in[5];
    const float* suw = (const float*)d_in[6];
    const float* sdw = (const float*)d_in[7];
    float* out = (float*)d_out;

    cudaFuncSetAttribute(gateup_mma_kernel,
                         cudaFuncAttributeMaxDynamicSharedMemorySize, SMEM_GATEUP);
    cudaFuncSetAttribute(down_mma_kernel,
                         cudaFuncAttributeMaxDynamicSharedMemorySize, SMEM_DOWN);

    cudaMemsetAsync(out, 0, (size_t)4194304 * sizeof(float), 0);
    zero_misc_kernel<<<1, 32>>>();
    router_kernel<<<T_TOK, 128>>>(x, rw, out);
    offsets_kernel<<<1, 1>>>();
    gateup_mma_kernel<<<dim3(IDIM / 128, T_TOK / 128, NE), 256, SMEM_GATEUP>>>(
        x, gw, uw, sgw, suw);
    down_mma_kernel<<<dim3(HDIM / 256, T_TOK / 128, NE), 256, SMEM_DOWN>>>(dw, sdw, out);
    finalize_kernel<<<1, 32>>>(out);
}

// round 16
// speedup vs baseline: 1.3577x; 1.3577x over previous
#include <cuda_runtime.h>
#include <cstdint>
#include <math.h>

#define T_TOK 4096
#define HDIM  1024
#define IDIM  2048
#define NEXP  8
#define NE    9      // 8 routed + 1 shared pseudo-expert

#define OFF_AUX 4194304
#define OFF_Z   4194305
#define OFF_LOG 4194306

// Scratch (alloc-free rule): activations + pre-tf32-rounded operands
__device__ float g_act[12288 * 2048];                 // 100 MB
__device__ float g_xc[T_TOK * HDIM];                  // 16 MB
__device__ float g_gwc[(size_t)NE * HDIM * IDIM];     // 72 MB  [e][H][I]
__device__ float g_uwc[(size_t)NE * HDIM * IDIM];     // 72 MB
__device__ float g_dwc[(size_t)NE * IDIM * HDIM];     // 72 MB  [e][I][H]
__device__ int   g_cnt[NEXP];
__device__ int   g_off[NEXP];
__device__ int   g_tok[NEXP * T_TOK];
__device__ float g_wt[NEXP * T_TOK];
__device__ float g_disp[NEXP];
__device__ float g_prob[NEXP];
__device__ float g_zsum;

// ---------------------------------------------------------------------------
__device__ __forceinline__ float to_tf32(float x) {
    uint32_t u; asm("cvt.rna.tf32.f32 %0, %1;" : "=r"(u) : "f"(x));
    return __uint_as_float(u);
}
__device__ __forceinline__ uint32_t smem_u32(const void* p) {
    uint32_t a;
    asm("{ .reg .u64 t; cvta.to.shared.u64 t, %1; cvt.u32.u64 %0, t; }"
        : "=r"(a) : "l"(p));
    return a;
}
__device__ __forceinline__ void cpa16(uint32_t dst, const void* src) {
    asm volatile("cp.async.cg.shared.global [%0], [%1], 16;" :: "r"(dst), "l"(src));
}
__device__ __forceinline__ void cpa_commit() {
    asm volatile("cp.async.commit_group;" ::: "memory");
}
__device__ __forceinline__ void cpa_wait1() {
    asm volatile("cp.async.wait_group 1;" ::: "memory");
}
__device__ __forceinline__ void cpa_wait0() {
    asm volatile("cp.async.wait_group 0;" ::: "memory");
}
// D += A(16x8) * B(8x8), tf32 inputs, f32 accum
__device__ __forceinline__ void mma8(float* d, const uint32_t* a, const uint32_t* b) {
    asm volatile(
        "mma.sync.aligned.m16n8k8.row.col.f32.tf32.tf32.f32 "
        "{%0,%1,%2,%3}, {%4,%5,%6,%7}, {%8,%9}, {%0,%1,%2,%3};"
        : "+f"(d[0]), "+f"(d[1]), "+f"(d[2]), "+f"(d[3])
        : "r"(a[0]), "r"(a[1]), "r"(a[2]), "r"(a[3]), "r"(b[0]), "r"(b[1]));
}
__device__ __forceinline__ uint32_t fb(float x) { return __float_as_uint(x); }

#define LDAK 36    // A tile row stride (32 k + 4 pad): (36g+tig)%32 conflict-free
#define LDB  72    // gateup B tiles: 64 n + 8 pad
#define LDB2 136   // down B tile: 128 n + 8 pad

// ---------------------------------------------------------------------------
__global__ void zero_misc_kernel() {
    int i = threadIdx.x;
    if (i < NEXP) { g_cnt[i] = 0; g_disp[i] = 0.f; g_prob[i] = 0.f; }
    if (i == 0) g_zsum = 0.f;
}

// ---------------------------------------------------------------------------
// Grid-stride tf32 rounding into a selected scratch destination.
__global__ void cvt_kernel(const float4* __restrict__ src, int dst_id,
                           size_t dst_off_f, int n4) {
    float4* dst;
    switch (dst_id) {
        case 0:  dst = (float4*)g_xc;  break;
        case 1:  dst = (float4*)g_gwc; break;
        case 2:  dst = (float4*)g_uwc; break;
        default: dst = (float4*)g_dwc; break;
    }
    dst += dst_off_f / 4;
    for (int i = blockIdx.x * blockDim.x + threadIdx.x; i < n4;
         i += gridDim.x * blockDim.x) {
        float4 v = src[i];
        v.x = to_tf32(v.x); v.y = to_tf32(v.y);
        v.z = to_tf32(v.z); v.w = to_tf32(v.w);
        dst[i] = v;
    }
}

// ---------------------------------------------------------------------------
__global__ void router_kernel(const float* __restrict__ x,
                              const float* __restrict__ rw,
                              float* __restrict__ out) {
    int t = blockIdx.x;
    const float* xr = x + (size_t)t * HDIM;

    float acc[NEXP];
#pragma unroll
    for (int e = 0; e < NEXP; e++) acc[e] = 0.f;

    for (int h = threadIdx.x; h < HDIM; h += 128) {
        float xv = xr[h];
        const float4* w = (const float4*)(rw + (size_t)h * NEXP);
        float4 w0 = w[0], w1 = w[1];
        acc[0] += xv * w0.x; acc[1] += xv * w0.y;
        acc[2] += xv * w0.z; acc[3] += xv * w0.w;
        acc[4] += xv * w1.x; acc[5] += xv * w1.y;
        acc[6] += xv * w1.z; acc[7] += xv * w1.w;
    }

    __shared__ float red[128][NEXP];
    __shared__ float lg[NEXP];
#pragma unroll
    for (int e = 0; e < NEXP; e++) red[threadIdx.x][e] = acc[e];
    __syncthreads();

    if (threadIdx.x < NEXP) {
        float s = 0.f;
        for (int i = 0; i < 128; i++) s += red[i][threadIdx.x];
        lg[threadIdx.x] = s;
    }
    __syncthreads();

    if (threadIdx.x == 0) {
        float mx = lg[0];
#pragma unroll
        for (int e = 1; e < NEXP; e++) mx = fmaxf(mx, lg[e]);
        float p[NEXP]; float sum = 0.f;
#pragma unroll
        for (int e = 0; e < NEXP; e++) { p[e] = expf(lg[e] - mx); sum += p[e]; }
        float lse = mx + logf(sum);
        atomicAdd(&g_zsum, lse * lse);
        float inv = 1.f / sum;

        int i0 = 0; float b0 = -1.f;
#pragma unroll
        for (int e = 0; e < NEXP; e++) {
            p[e] *= inv;
            if (p[e] > b0) { b0 = p[e]; i0 = e; }
            atomicAdd(&g_prob[e], p[e]);
            out[OFF_LOG + (size_t)t * NEXP + e] = lg[e];
        }
        int i1 = -1; float b1 = -1.f;
#pragma unroll
        for (int e = 0; e < NEXP; e++) {
            if (e != i0 && p[e] > b1) { b1 = p[e]; i1 = e; }
        }
        float s2 = b0 + b1;
        float w0 = b0 / s2, w1 = b1 / s2;

        int s0 = atomicAdd(&g_cnt[i0], 1);
        g_tok[i0 * T_TOK + s0] = t; g_wt[i0 * T_TOK + s0] = w0;
        int s1 = atomicAdd(&g_cnt[i1], 1);
        g_tok[i1 * T_TOK + s1] = t; g_wt[i1 * T_TOK + s1] = w1;
        atomicAdd(&g_disp[i0], 0.5f);
        atomicAdd(&g_disp[i1], 0.5f);
    }
}

__global__ void offsets_kernel() {
    int o = 0;
    for (int e = 0; e < NEXP; e++) { g_off[e] = o; o += g_cnt[e]; }
}

// ---------------------------------------------------------------------------
// Pass A: gate/up GEMM. Block tile M=128, N=64, K=32, cp.async double-buffer.
// 8 warps: wm=w&3 (32 rows), wn=w>>2 (32 cols). Warp tile 32x32 per matrix.
// SMEM stage: As[128][36] + Bg[32][72] + Bu[32][72].
__global__ __launch_bounds__(256, 2) void gateup_mma_kernel() {
    extern __shared__ __align__(16) float smem[];
    const int A_SZ = 128 * LDAK;         // 4608 floats
    const int B_SZ = 32 * LDB;           // 2304 floats
    const int STG  = A_SZ + 2 * B_SZ;    // 9216 floats

    int e = blockIdx.z;
    int cnt = (e < NEXP) ? g_cnt[e] : T_TOK;
    int row0 = blockIdx.y * 128;
    if (row0 >= cnt) return;
    int base = (e < NEXP) ? g_off[e] : 2 * T_TOK;
    int n0 = blockIdx.x * 64;
    const float* gw = g_gwc + (size_t)e * HDIM * IDIM;
    const float* uw = g_uwc + (size_t)e * HDIM * IDIM;

    __shared__ int s_tok[128];

    int tid = threadIdx.x;
    int w = tid >> 5, lane = tid & 31;
    int g = lane >> 2, tig = lane & 3;
    int wm = w & 3, wn = w >> 2;

    if (tid < 128) {
        int r = row0 + tid;
        s_tok[tid] = (r < cnt) ? ((e < NEXP) ? g_tok[e * T_TOK + r] : r) : -1;
    }
    __syncthreads();

    uint32_t sb = smem_u32(smem);

    // A copy assignments: 4 16B segments/thread; q = tid + 256*i -> m=q>>3, seg=q&7
    const float* aptr[4];
    uint32_t adst[4];
#pragma unroll
    for (int i = 0; i < 4; i++) {
        int q = tid + 256 * i;
        int m = q >> 3, seg = q & 7;
        aptr[i] = g_xc + (size_t)max(s_tok[m], 0) * HDIM + seg * 4;
        adst[i] = sb + (uint32_t)(m * LDAK + seg * 4) * 4;
    }
    // B copy: 2 segs per matrix per thread; q = tid + 256*i -> r=q>>4, seg=q&15
    const float* gptrB[2]; const float* uptrB[2];
    uint32_t gdst[2], udst[2];
#pragma unroll
    for (int i = 0; i < 2; i++) {
        int q = tid + 256 * i;
        int r = q >> 4, seg = q & 15;
        gptrB[i] = gw + (size_t)r * IDIM + n0 + seg * 4;
        uptrB[i] = uw + (size_t)r * IDIM + n0 + seg * 4;
        gdst[i] = sb + (uint32_t)(A_SZ + r * LDB + seg * 4) * 4;
        udst[i] = sb + (uint32_t)(A_SZ + B_SZ + r * LDB + seg * 4) * 4;
    }

    auto stage = [&](int c, int b) {
        int k0 = c * 32;
        uint32_t so = (uint32_t)(b * STG) * 4;
#pragma unroll
        for (int i = 0; i < 4; i++) cpa16(adst[i] + so, aptr[i] + k0);
#pragma unroll
        for (int i = 0; i < 2; i++) {
            cpa16(gdst[i] + so, gptrB[i] + (size_t)k0 * IDIM);
            cpa16(udst[i] + so, uptrB[i] + (size_t)k0 * IDIM);
        }
        cpa_commit();
    };

    float cg[2][4][4], cu[2][4][4];
#pragma unroll
    for (int mi = 0; mi < 2; mi++)
#pragma unroll
        for (int j = 0; j < 4; j++)
#pragma unroll
            for (int q = 0; q < 4; q++) { cg[mi][j][q] = 0.f; cu[mi][j][q] = 0.f; }

    const int NK = HDIM / 32;  // 32
    stage(0, 0);

    for (int c = 0; c < NK; c++) {
        int b = c & 1;
        if (c + 1 < NK) { stage(c + 1, b ^ 1); cpa_wait1(); }
        else cpa_wait0();
        __syncthreads();

        const float* As = smem + b * STG;
        const float* Bg = As + A_SZ;
        const float* Bu = Bg + B_SZ;
#pragma unroll
        for (int kq = 0; kq < 4; kq++) {
            int kk = kq * 8;
            uint32_t a[2][4];
#pragma unroll
            for (int mi = 0; mi < 2; mi++) {
                int m0 = wm * 32 + mi * 16;
                a[mi][0] = fb(As[(m0 + g) * LDAK + kk + tig]);
                a[mi][1] = fb(As[(m0 + 8 + g) * LDAK + kk + tig]);
                a[mi][2] = fb(As[(m0 + g) * LDAK + kk + 4 + tig]);
                a[mi][3] = fb(As[(m0 + 8 + g) * LDAK + kk + 4 + tig]);
            }
            uint32_t bg[4][2], bu[4][2];
#pragma unroll
            for (int j = 0; j < 4; j++) {
                int n = wn * 32 + j * 8 + g;
                bg[j][0] = fb(Bg[(kk + tig) * LDB + n]);
                bg[j][1] = fb(Bg[(kk + 4 + tig) * LDB + n]);
                bu[j][0] = fb(Bu[(kk + tig) * LDB + n]);
                bu[j][1] = fb(Bu[(kk + 4 + tig) * LDB + n]);
            }
#pragma unroll
            for (int mi = 0; mi < 2; mi++)
#pragma unroll
                for (int j = 0; j < 4; j++) {
                    mma8(cg[mi][j], a[mi], bg[j]);
                    mma8(cu[mi][j], a[mi], bu[j]);
                }
        }
        __syncthreads();
    }

    // Epilogue: silu(gate)*up, tf32-rounded, -> g_act
#pragma unroll
    for (int mi = 0; mi < 2; mi++) {
#pragma unroll
        for (int half = 0; half < 2; half++) {
            int r = wm * 32 + mi * 16 + half * 8 + g;
            if (s_tok[r] < 0) continue;
            float* dst = g_act + (size_t)(base + row0 + r) * IDIM + n0 + wn * 32 + 2 * tig;
#pragma unroll
            for (int j = 0; j < 4; j++) {
                float gv0 = cg[mi][j][half * 2 + 0], uv0 = cu[mi][j][half * 2 + 0];
                float gv1 = cg[mi][j][half * 2 + 1], uv1 = cu[mi][j][half * 2 + 1];
                float2 v;
                v.x = to_tf32((gv0 / (1.f + __expf(-gv0))) * uv0);
                v.y = to_tf32((gv1 / (1.f + __expf(-gv1))) * uv1);
                *(float2*)(dst + j * 8) = v;
            }
        }
    }
}

// ---------------------------------------------------------------------------
// Pass B: out[tok] += w * (act_row @ down_w). Block tile M=128, N=128, K=32.
// 8 warps: wm=w&3 (32 rows), wn=w>>2 (64 cols). Warp tile 32x64.
__global__ __launch_bounds__(256, 2) void down_mma_kernel(float* __restrict__ out) {
    extern __shared__ __align__(16) float smem[];
    const int A_SZ = 128 * LDAK;         // 4608
    const int B_SZ = 32 * LDB2;          // 4352
    const int STG  = A_SZ + B_SZ;        // 8960 floats

    int e = blockIdx.z;
    int cnt = (e < NEXP) ? g_cnt[e] : T_TOK;
    int row0 = blockIdx.y * 128;
    if (row0 >= cnt) return;
    int base = (e < NEXP) ? g_off[e] : 2 * T_TOK;
    int n0 = blockIdx.x * 128;
    const float* dw = g_dwc + (size_t)e * IDIM * HDIM;

    __shared__ int   s_tok[128];
    __shared__ float s_w[128];

    int tid = threadIdx.x;
    int w = tid >> 5, lane = tid & 31;
    int g = lane >> 2, tig = lane & 3;
    int wm = w & 3, wn = w >> 2;

    if (tid < 128) {
        int r = row0 + tid;
        if (r < cnt) {
            s_tok[tid] = (e < NEXP) ? g_tok[e * T_TOK + r] : r;
            s_w[tid]   = (e < NEXP) ? g_wt[e * T_TOK + r] : 1.0f;
        } else { s_tok[tid] = -1; s_w[tid] = 0.f; }
    }
    __syncthreads();

    uint32_t sb = smem_u32(smem);

    // A: rows are contiguous in g_act starting at base+row0
    const float* aptr[4];
    uint32_t adst[4];
#pragma unroll
    for (int i = 0; i < 4; i++) {
        int q = tid + 256 * i;
        int m = q >> 3, seg = q & 7;
        aptr[i] = g_act + (size_t)(base + row0 + m) * IDIM + seg * 4;
        adst[i] = sb + (uint32_t)(m * LDAK + seg * 4) * 4;
    }
    // B: 4 segs/thread; q = tid + 256*i -> r=q>>5, seg=q&31
    const float* bptr[4];
    uint32_t bdst[4];
#pragma unroll
    for (int i = 0; i < 4; i++) {
        int q = tid + 256 * i;
        int r = q >> 5, seg = q & 31;
        bptr[i] = dw + (size_t)r * HDIM + n0 + seg * 4;
        bdst[i] = sb + (uint32_t)(A_SZ + r * LDB2 + seg * 4) * 4;
    }

    auto stage = [&](int c, int b) {
        int k0 = c * 32;
        uint32_t so = (uint32_t)(b * STG) * 4;
#pragma unroll
        for (int i = 0; i < 4; i++) cpa16(adst[i] + so, aptr[i] + k0);
#pragma unroll
        for (int i = 0; i < 4; i++) cpa16(bdst[i] + so, bptr[i] + (size_t)k0 * HDIM);
        cpa_commit();
    };

    float acc[2][8][4];
#pragma unroll
    for (int mi = 0; mi < 2; mi++)
#pragma unroll
        for (int j = 0; j < 8; j++)
#pragma unroll
            for (int q = 0; q < 4; q++) acc[mi][j][q] = 0.f;

    const int NK = IDIM / 32;  // 64
    stage(0, 0);

    for (int c = 0; c < NK; c++) {
        int b = c & 1;
        if (c + 1 < NK) { stage(c + 1, b ^ 1); cpa_wait1(); }
        else cpa_wait0();
        __syncthreads();

        const float* As = smem + b * STG;
        const float* Bs = As + A_SZ;
#pragma unroll
        for (int kq = 0; kq < 4; kq++) {
            int kk = kq * 8;
            uint32_t a[2][4];
#pragma unroll
            for (int mi = 0; mi < 2; mi++) {
                int m0 = wm * 32 + mi * 16;
                a[mi][0] = fb(As[(m0 + g) * LDAK + kk + tig]);
                a[mi][1] = fb(As[(m0 + 8 + g) * LDAK + kk + tig]);
                a[mi][2] = fb(As[(m0 + g) * LDAK + kk + 4 + tig]);
                a[mi][3] = fb(As[(m0 + 8 + g) * LDAK + kk + 4 + tig]);
            }
            uint32_t bf[8][2];
#pragma unroll
            for (int j = 0; j < 8; j++) {
                int n = wn * 64 + j * 8 + g;
                bf[j][0] = fb(Bs[(kk + tig) * LDB2 + n]);
                bf[j][1] = fb(Bs[(kk + 4 + tig) * LDB2 + n]);
            }
#pragma unroll
            for (int mi = 0; mi < 2; mi++)
#pragma unroll
                for (int j = 0; j < 8; j++)
                    mma8(acc[mi][j], a[mi], bf[j]);
        }
        __syncthreads();
    }

    // Epilogue: scale by router weight, atomicAdd into out
#pragma unroll
    for (int mi = 0; mi < 2; mi++) {
#pragma unroll
        for (int half = 0; half < 2; half++) {
            int r = wm * 32 + mi * 16 + half * 8 + g;
            int tok = s_tok[r];
            if (tok < 0) continue;
            float wr = s_w[r];
            float* dst = out + (size_t)tok * HDIM + n0 + wn * 64 + 2 * tig;
#pragma unroll
            for (int j = 0; j < 8; j++) {
                atomicAdd(dst + j * 8 + 0, wr * acc[mi][j][half * 2 + 0]);
                atomicAdd(dst + j * 8 + 1, wr * acc[mi][j][half * 2 + 1]);
            }
        }
    }
}

// ---------------------------------------------------------------------------
__global__ void finalize_kernel(float* __restrict__ out) {
    if (threadIdx.x == 0) {
        float aux = 0.f;
        for (int e = 0; e < NEXP; e++)
            aux += (g_disp[e] / (float)T_TOK) * (g_prob[e] / (float)T_TOK);
        out[OFF_AUX] = (float)NEXP * aux;
        out[OFF_Z]   = g_zsum / (float)T_TOK;
    }
}

// ---------------------------------------------------------------------------
#define SMEM_GATEUP (2 * (128 * LDAK + 2 * 32 * LDB) * 4)   // 73728 B
#define SMEM_DOWN   (2 * (128 * LDAK + 32 * LDB2) * 4)      // 71680 B

extern "C" void kernel_launch(void* const* d_in, const int* in_sizes, int n_in,
                              void* d_out, int out_size) {
    const float* x   = (const float*)d_in[0];
    const float* rw  = (const float*)d_in[1];
    const float* gw  = (const float*)d_in[2];
    const float* uw  = (const float*)d_in[3];
    const float* dw  = (const float*)d_in[4];
    const float* sgw = (const float*)d_in[5];
    const float* suw = (const float*)d_in[6];
    const float* sdw = (const float*)d_in[7];
    float* out = (float*)d_out;

    cudaFuncSetAttribute(gateup_mma_kernel,
                         cudaFuncAttributeMaxDynamicSharedMemorySize, SMEM_GATEUP);
    cudaFuncSetAttribute(down_mma_kernel,
                         cudaFuncAttributeMaxDynamicSharedMemorySize, SMEM_DOWN);

    cudaMemsetAsync(out, 0, (size_t)4194304 * sizeof(float), 0);
    zero_misc_kernel<<<1, 32>>>();
    router_kernel<<<T_TOK, 128>>>(x, rw, out);
    offsets_kernel<<<1, 1>>>();

    const size_t EW = (size_t)HDIM * IDIM;   // 2M floats per expert matrix
    cvt_kernel<<<2048, 256>>>((const float4*)x,   0, 0,            T_TOK * HDIM / 4);
    cvt_kernel<<<4096, 256>>>((const float4*)gw,  1, 0,            (int)(8 * EW / 4));
    cvt_kernel<<<1024, 256>>>((const float4*)sgw, 1, 8 * EW,       (int)(EW / 4));
    cvt_kernel<<<4096, 256>>>((const float4*)uw,  2, 0,            (int)(8 * EW / 4));
    cvt_kernel<<<1024, 256>>>((const float4*)suw, 2, 8 * EW,       (int)(EW / 4));
    cvt_kernel<<<4096, 256>>>((const float4*)dw,  3, 0,            (int)(8 * EW / 4));
    cvt_kernel<<<1024, 256>>>((const float4*)sdw, 3, 8 * EW,       (int)(EW / 4));

    gateup_mma_kernel<<<dim3(IDIM / 64, T_TOK / 128, NE), 256, SMEM_GATEUP>>>();
    down_mma_kernel<<<dim3(HDIM / 128, T_TOK / 128, NE), 256, SMEM_DOWN>>>(out);
    finalize_kernel<<<1, 32>>>(out);
}

// round 17
// speedup vs baseline: 1.3582x; 1.0004x over previous
#include <cuda_runtime.h>
#include <cstdint>
#include <math.h>

#define T_TOK 4096
#define HDIM  1024
#define IDIM  2048
#define NEXP  8
#define NE    9      // 8 routed + 1 shared pseudo-expert

#define OFF_AUX 4194304
#define OFF_Z   4194305
#define OFF_LOG 4194306

// Scratch (alloc-free rule): activations + pre-tf32-rounded operands
__device__ float g_act[12288 * 2048];                 // 100 MB
__device__ float g_xc[T_TOK * HDIM];                  // 16 MB
__device__ float g_gwc[(size_t)NE * HDIM * IDIM];     // 72 MB  [e][H][I]
__device__ float g_uwc[(size_t)NE * HDIM * IDIM];     // 72 MB
__device__ float g_dwc[(size_t)NE * IDIM * HDIM];     // 72 MB  [e][I][H]
__device__ int   g_cnt[NEXP];
__device__ int   g_off[NEXP];
__device__ int   g_tok[NEXP * T_TOK];
__device__ float g_wt[NEXP * T_TOK];
__device__ float g_disp[NEXP];
__device__ float g_prob[NEXP];
__device__ float g_zsum;

// ---------------------------------------------------------------------------
__device__ __forceinline__ float to_tf32(float x) {
    uint32_t u; asm("cvt.rna.tf32.f32 %0, %1;" : "=r"(u) : "f"(x));
    return __uint_as_float(u);
}
__device__ __forceinline__ uint32_t smem_u32(const void* p) {
    uint32_t a;
    asm("{ .reg .u64 t; cvta.to.shared.u64 t, %1; cvt.u32.u64 %0, t; }"
        : "=r"(a) : "l"(p));
    return a;
}
__device__ __forceinline__ void cpa16(uint32_t dst, const void* src) {
    asm volatile("cp.async.cg.shared.global [%0], [%1], 16;" :: "r"(dst), "l"(src));
}
__device__ __forceinline__ void cpa_commit() {
    asm volatile("cp.async.commit_group;" ::: "memory");
}
__device__ __forceinline__ void cpa_wait1() {
    asm volatile("cp.async.wait_group 1;" ::: "memory");
}
__device__ __forceinline__ void cpa_wait0() {
    asm volatile("cp.async.wait_group 0;" ::: "memory");
}
// D += A(16x8) * B(8x8), tf32 inputs, f32 accum
__device__ __forceinline__ void mma8(float* d, const uint32_t* a, const uint32_t* b) {
    asm volatile(
        "mma.sync.aligned.m16n8k8.row.col.f32.tf32.tf32.f32 "
        "{%0,%1,%2,%3}, {%4,%5,%6,%7}, {%8,%9}, {%0,%1,%2,%3};"
        : "+f"(d[0]), "+f"(d[1]), "+f"(d[2]), "+f"(d[3])
        : "r"(a[0]), "r"(a[1]), "r"(a[2]), "r"(a[3]), "r"(b[0]), "r"(b[1]));
}
__device__ __forceinline__ uint32_t fb(float x) { return __float_as_uint(x); }

#define LDAK 36    // A tile row stride (32 k + 4 pad): (36g+tig)%32 conflict-free
#define LDB  72    // gateup B tiles: 64 n + 8 pad
#define LDB2 136   // down B tile: 128 n + 8 pad

// ---------------------------------------------------------------------------
__global__ void zero_misc_kernel() {
    int i = threadIdx.x;
    if (i < NEXP) { g_cnt[i] = 0; g_disp[i] = 0.f; g_prob[i] = 0.f; }
    if (i == 0) g_zsum = 0.f;
}

// ---------------------------------------------------------------------------
// Merged tf32 rounding for ALL operands in one launch, explicit 4-way MLP.
#define CVT_XN4 1048576              // x: 4M floats
#define CVT_EN4 524288               // one expert matrix: 2M floats
#define CVT_W84 (8 * CVT_EN4)        // 8 routed expert matrices
#define CVT_TOTAL (CVT_XN4 + 3 * (CVT_W84 + CVT_EN4))   // 15,204,352 float4

__global__ __launch_bounds__(256) void cvt_all_kernel(
    const float4* __restrict__ x,
    const float4* __restrict__ gw, const float4* __restrict__ sgw,
    const float4* __restrict__ uw, const float4* __restrict__ suw,
    const float4* __restrict__ dw, const float4* __restrict__ sdw) {
    int nth = gridDim.x * blockDim.x;
    int i0 = blockIdx.x * blockDim.x + threadIdx.x;

    const float4* src[4];
    float4* dst[4];
    int nv = 0;
#pragma unroll
    for (int u = 0; u < 4; u++) {
        long i = (long)i0 + (long)u * nth;
        if (i >= CVT_TOTAL) break;
        long j = i;
        const float4* s; float4* d;
        if (j < CVT_XN4) { s = x + j; d = (float4*)g_xc + j; }
        else {
            j -= CVT_XN4;
            if (j < CVT_W84) { s = gw + j; d = (float4*)g_gwc + j; }
            else { j -= CVT_W84;
            if (j < CVT_EN4) { s = sgw + j; d = (float4*)g_gwc + CVT_W84 + j; }
            else { j -= CVT_EN4;
            if (j < CVT_W84) { s = uw + j; d = (float4*)g_uwc + j; }
            else { j -= CVT_W84;
            if (j < CVT_EN4) { s = suw + j; d = (float4*)g_uwc + CVT_W84 + j; }
            else { j -= CVT_EN4;
            if (j < CVT_W84) { s = dw + j; d = (float4*)g_dwc + j; }
            else { j -= CVT_W84; s = sdw + j; d = (float4*)g_dwc + CVT_W84 + j; }}}}}
        }
        src[nv] = s; dst[nv] = d; nv++;
    }
    float4 v[4];
#pragma unroll
    for (int u = 0; u < 4; u++) if (u < nv) v[u] = *src[u];
#pragma unroll
    for (int u = 0; u < 4; u++) if (u < nv) {
        v[u].x = to_tf32(v[u].x); v[u].y = to_tf32(v[u].y);
        v[u].z = to_tf32(v[u].z); v[u].w = to_tf32(v[u].w);
        *dst[u] = v[u];
    }
}

// ---------------------------------------------------------------------------
__global__ void router_kernel(const float* __restrict__ x,
                              const float* __restrict__ rw,
                              float* __restrict__ out) {
    int t = blockIdx.x;
    const float* xr = x + (size_t)t * HDIM;

    float acc[NEXP];
#pragma unroll
    for (int e = 0; e < NEXP; e++) acc[e] = 0.f;

    for (int h = threadIdx.x; h < HDIM; h += 128) {
        float xv = xr[h];
        const float4* w = (const float4*)(rw + (size_t)h * NEXP);
        float4 w0 = w[0], w1 = w[1];
        acc[0] += xv * w0.x; acc[1] += xv * w0.y;
        acc[2] += xv * w0.z; acc[3] += xv * w0.w;
        acc[4] += xv * w1.x; acc[5] += xv * w1.y;
        acc[6] += xv * w1.z; acc[7] += xv * w1.w;
    }

    __shared__ float red[128][NEXP];
    __shared__ float lg[NEXP];
#pragma unroll
    for (int e = 0; e < NEXP; e++) red[threadIdx.x][e] = acc[e];
    __syncthreads();

    if (threadIdx.x < NEXP) {
        float s = 0.f;
        for (int i = 0; i < 128; i++) s += red[i][threadIdx.x];
        lg[threadIdx.x] = s;
    }
    __syncthreads();

    if (threadIdx.x == 0) {
        float mx = lg[0];
#pragma unroll
        for (int e = 1; e < NEXP; e++) mx = fmaxf(mx, lg[e]);
        float p[NEXP]; float sum = 0.f;
#pragma unroll
        for (int e = 0; e < NEXP; e++) { p[e] = expf(lg[e] - mx); sum += p[e]; }
        float lse = mx + logf(sum);
        atomicAdd(&g_zsum, lse * lse);
        float inv = 1.f / sum;

        int i0 = 0; float b0 = -1.f;
#pragma unroll
        for (int e = 0; e < NEXP; e++) {
            p[e] *= inv;
            if (p[e] > b0) { b0 = p[e]; i0 = e; }
            atomicAdd(&g_prob[e], p[e]);
            out[OFF_LOG + (size_t)t * NEXP + e] = lg[e];
        }
        int i1 = -1; float b1 = -1.f;
#pragma unroll
        for (int e = 0; e < NEXP; e++) {
            if (e != i0 && p[e] > b1) { b1 = p[e]; i1 = e; }
        }
        float s2 = b0 + b1;
        float w0 = b0 / s2, w1 = b1 / s2;

        int s0 = atomicAdd(&g_cnt[i0], 1);
        g_tok[i0 * T_TOK + s0] = t; g_wt[i0 * T_TOK + s0] = w0;
        int s1 = atomicAdd(&g_cnt[i1], 1);
        g_tok[i1 * T_TOK + s1] = t; g_wt[i1 * T_TOK + s1] = w1;
        atomicAdd(&g_disp[i0], 0.5f);
        atomicAdd(&g_disp[i1], 0.5f);
    }
}

__global__ void offsets_kernel() {
    int o = 0;
    for (int e = 0; e < NEXP; e++) { g_off[e] = o; o += g_cnt[e]; }
}

// ---------------------------------------------------------------------------
// Pass A: gate/up GEMM. Block tile M=128, N=64, K=32.
// 3-stage cp.async pipeline, ONE __syncthreads per k-chunk.
// 8 warps: wm=w&3 (32 rows), wn=w>>2 (32 cols). Warp tile 32x32 per matrix.
__global__ __launch_bounds__(256, 2) void gateup_mma_kernel() {
    extern __shared__ __align__(16) float smem[];
    const int A_SZ = 128 * LDAK;         // 4608 floats
    const int B_SZ = 32 * LDB;           // 2304 floats
    const int STG  = A_SZ + 2 * B_SZ;    // 9216 floats per stage

    int e = blockIdx.z;
    int cnt = (e < NEXP) ? g_cnt[e] : T_TOK;
    int row0 = blockIdx.y * 128;
    if (row0 >= cnt) return;
    int base = (e < NEXP) ? g_off[e] : 2 * T_TOK;
    int n0 = blockIdx.x * 64;
    const float* gw = g_gwc + (size_t)e * HDIM * IDIM;
    const float* uw = g_uwc + (size_t)e * HDIM * IDIM;

    __shared__ int s_tok[128];

    int tid = threadIdx.x;
    int w = tid >> 5, lane = tid & 31;
    int g = lane >> 2, tig = lane & 3;
    int wm = w & 3, wn = w >> 2;

    if (tid < 128) {
        int r = row0 + tid;
        s_tok[tid] = (r < cnt) ? ((e < NEXP) ? g_tok[e * T_TOK + r] : r) : -1;
    }
    __syncthreads();

    uint32_t sb = smem_u32(smem);

    const float* aptr[4];
    uint32_t adst[4];
#pragma unroll
    for (int i = 0; i < 4; i++) {
        int q = tid + 256 * i;
        int m = q >> 3, seg = q & 7;
        aptr[i] = g_xc + (size_t)max(s_tok[m], 0) * HDIM + seg * 4;
        adst[i] = sb + (uint32_t)(m * LDAK + seg * 4) * 4;
    }
    const float* gptrB[2]; const float* uptrB[2];
    uint32_t gdst[2], udst[2];
#pragma unroll
    for (int i = 0; i < 2; i++) {
        int q = tid + 256 * i;
        int r = q >> 4, seg = q & 15;
        gptrB[i] = gw + (size_t)r * IDIM + n0 + seg * 4;
        uptrB[i] = uw + (size_t)r * IDIM + n0 + seg * 4;
        gdst[i] = sb + (uint32_t)(A_SZ + r * LDB + seg * 4) * 4;
        udst[i] = sb + (uint32_t)(A_SZ + B_SZ + r * LDB + seg * 4) * 4;
    }

    auto stage = [&](int c, int b) {
        int k0 = c * 32;
        uint32_t so = (uint32_t)(b * STG) * 4;
#pragma unroll
        for (int i = 0; i < 4; i++) cpa16(adst[i] + so, aptr[i] + k0);
#pragma unroll
        for (int i = 0; i < 2; i++) {
            cpa16(gdst[i] + so, gptrB[i] + (size_t)k0 * IDIM);
            cpa16(udst[i] + so, uptrB[i] + (size_t)k0 * IDIM);
        }
        cpa_commit();
    };

    float cg[2][4][4], cu[2][4][4];
#pragma unroll
    for (int mi = 0; mi < 2; mi++)
#pragma unroll
        for (int j = 0; j < 4; j++)
#pragma unroll
            for (int q = 0; q < 4; q++) { cg[mi][j][q] = 0.f; cu[mi][j][q] = 0.f; }

    const int NK = HDIM / 32;  // 32
    stage(0, 0);
    stage(1, 1);

    for (int c = 0; c < NK; c++) {
        if (c + 1 < NK) cpa_wait1(); else cpa_wait0();
        __syncthreads();   // buffer c arrived; all threads done with chunk c-1
        if (c + 2 < NK) stage(c + 2, (c + 2) % 3);

        int b = c % 3;
        const float* As = smem + b * STG;
        const float* Bg = As + A_SZ;
        const float* Bu = Bg + B_SZ;
#pragma unroll
        for (int kq = 0; kq < 4; kq++) {
            int kk = kq * 8;
            uint32_t a[2][4];
#pragma unroll
            for (int mi = 0; mi < 2; mi++) {
                int m0 = wm * 32 + mi * 16;
                a[mi][0] = fb(As[(m0 + g) * LDAK + kk + tig]);
                a[mi][1] = fb(As[(m0 + 8 + g) * LDAK + kk + tig]);
                a[mi][2] = fb(As[(m0 + g) * LDAK + kk + 4 + tig]);
                a[mi][3] = fb(As[(m0 + 8 + g) * LDAK + kk + 4 + tig]);
            }
            uint32_t bg[4][2], bu[4][2];
#pragma unroll
            for (int j = 0; j < 4; j++) {
                int n = wn * 32 + j * 8 + g;
                bg[j][0] = fb(Bg[(kk + tig) * LDB + n]);
                bg[j][1] = fb(Bg[(kk + 4 + tig) * LDB + n]);
                bu[j][0] = fb(Bu[(kk + tig) * LDB + n]);
                bu[j][1] = fb(Bu[(kk + 4 + tig) * LDB + n]);
            }
#pragma unroll
            for (int mi = 0; mi < 2; mi++)
#pragma unroll
                for (int j = 0; j < 4; j++) {
                    mma8(cg[mi][j], a[mi], bg[j]);
                    mma8(cu[mi][j], a[mi], bu[j]);
                }
        }
    }

    // Epilogue: silu(gate)*up, tf32-rounded, -> g_act
#pragma unroll
    for (int mi = 0; mi < 2; mi++) {
#pragma unroll
        for (int half = 0; half < 2; half++) {
            int r = wm * 32 + mi * 16 + half * 8 + g;
            if (s_tok[r] < 0) continue;
            float* dst = g_act + (size_t)(base + row0 + r) * IDIM + n0 + wn * 32 + 2 * tig;
#pragma unroll
            for (int j = 0; j < 4; j++) {
                float gv0 = cg[mi][j][half * 2 + 0], uv0 = cu[mi][j][half * 2 + 0];
                float gv1 = cg[mi][j][half * 2 + 1], uv1 = cu[mi][j][half * 2 + 1];
                float2 v;
                v.x = to_tf32((gv0 / (1.f + __expf(-gv0))) * uv0);
                v.y = to_tf32((gv1 / (1.f + __expf(-gv1))) * uv1);
                *(float2*)(dst + j * 8) = v;
            }
        }
    }
}

// ---------------------------------------------------------------------------
// Pass B: out[tok] += w * (act_row @ down_w). Block tile M=128, N=128, K=32.
// 3-stage cp.async pipeline, one sync per chunk. Warp tile 32x64.
__global__ __launch_bounds__(256, 2) void down_mma_kernel(float* __restrict__ out) {
    extern __shared__ __align__(16) float smem[];
    const int A_SZ = 128 * LDAK;         // 4608
    const int B_SZ = 32 * LDB2;          // 4352
    const int STG  = A_SZ + B_SZ;        // 8960 floats per stage

    int e = blockIdx.z;
    int cnt = (e < NEXP) ? g_cnt[e] : T_TOK;
    int row0 = blockIdx.y * 128;
    if (row0 >= cnt) return;
    int base = (e < NEXP) ? g_off[e] : 2 * T_TOK;
    int n0 = blockIdx.x * 128;
    const float* dw = g_dwc + (size_t)e * IDIM * HDIM;

    __shared__ int   s_tok[128];
    __shared__ float s_w[128];

    int tid = threadIdx.x;
    int w = tid >> 5, lane = tid & 31;
    int g = lane >> 2, tig = lane & 3;
    int wm = w & 3, wn = w >> 2;

    if (tid < 128) {
        int r = row0 + tid;
        if (r < cnt) {
            s_tok[tid] = (e < NEXP) ? g_tok[e * T_TOK + r] : r;
            s_w[tid]   = (e < NEXP) ? g_wt[e * T_TOK + r] : 1.0f;
        } else { s_tok[tid] = -1; s_w[tid] = 0.f; }
    }
    __syncthreads();

    uint32_t sb = smem_u32(smem);

    const float* aptr[4];
    uint32_t adst[4];
#pragma unroll
    for (int i = 0; i < 4; i++) {
        int q = tid + 256 * i;
        int m = q >> 3, seg = q & 7;
        aptr[i] = g_act + (size_t)(base + row0 + m) * IDIM + seg * 4;
        adst[i] = sb + (uint32_t)(m * LDAK + seg * 4) * 4;
    }
    const float* bptr[4];
    uint32_t bdst[4];
#pragma unroll
    for (int i = 0; i < 4; i++) {
        int q = tid + 256 * i;
        int r = q >> 5, seg = q & 31;
        bptr[i] = dw + (size_t)r * HDIM + n0 + seg * 4;
        bdst[i] = sb + (uint32_t)(A_SZ + r * LDB2 + seg * 4) * 4;
    }

    auto stage = [&](int c, int b) {
        int k0 = c * 32;
        uint32_t so = (uint32_t)(b * STG) * 4;
#pragma unroll
        for (int i = 0; i < 4; i++) cpa16(adst[i] + so, aptr[i] + k0);
#pragma unroll
        for (int i = 0; i < 4; i++) cpa16(bdst[i] + so, bptr[i] + (size_t)k0 * HDIM);
        cpa_commit();
    };

    float acc[2][8][4];
#pragma unroll
    for (int mi = 0; mi < 2; mi++)
#pragma unroll
        for (int j = 0; j < 8; j++)
#pragma unroll
            for (int q = 0; q < 4; q++) acc[mi][j][q] = 0.f;

    const int NK = IDIM / 32;  // 64
    stage(0, 0);
    stage(1, 1);

    for (int c = 0; c < NK; c++) {
        if (c + 1 < NK) cpa_wait1(); else cpa_wait0();
        __syncthreads();
        if (c + 2 < NK) stage(c + 2, (c + 2) % 3);

        int b = c % 3;
        const float* As = smem + b * STG;
        const float* Bs = As + A_SZ;
#pragma unroll
        for (int kq = 0; kq < 4; kq++) {
            int kk = kq * 8;
            uint32_t a[2][4];
#pragma unroll
            for (int mi = 0; mi < 2; mi++) {
                int m0 = wm * 32 + mi * 16;
                a[mi][0] = fb(As[(m0 + g) * LDAK + kk + tig]);
                a[mi][1] = fb(As[(m0 + 8 + g) * LDAK + kk + tig]);
                a[mi][2] = fb(As[(m0 + g) * LDAK + kk + 4 + tig]);
                a[mi][3] = fb(As[(m0 + 8 + g) * LDAK + kk + 4 + tig]);
            }
            uint32_t bf[8][2];
#pragma unroll
            for (int j = 0; j < 8; j++) {
                int n = wn * 64 + j * 8 + g;
                bf[j][0] = fb(Bs[(kk + tig) * LDB2 + n]);
                bf[j][1] = fb(Bs[(kk + 4 + tig) * LDB2 + n]);
            }
#pragma unroll
            for (int mi = 0; mi < 2; mi++)
#pragma unroll
                for (int j = 0; j < 8; j++)
                    mma8(acc[mi][j], a[mi], bf[j]);
        }
    }

    // Epilogue: scale by router weight, atomicAdd into out
#pragma unroll
    for (int mi = 0; mi < 2; mi++) {
#pragma unroll
        for (int half = 0; half < 2; half++) {
            int r = wm * 32 + mi * 16 + half * 8 + g;
            int tok = s_tok[r];
            if (tok < 0) continue;
            float wr = s_w[r];
            float* dst = out + (size_t)tok * HDIM + n0 + wn * 64 + 2 * tig;
#pragma unroll
            for (int j = 0; j < 8; j++) {
                atomicAdd(dst + j * 8 + 0, wr * acc[mi][j][half * 2 + 0]);
                atomicAdd(dst + j * 8 + 1, wr * acc[mi][j][half * 2 + 1]);
            }
        }
    }
}

// ---------------------------------------------------------------------------
__global__ void finalize_kernel(float* __restrict__ out) {
    if (threadIdx.x == 0) {
        float aux = 0.f;
        for (int e = 0; e < NEXP; e++)
            aux += (g_disp[e] / (float)T_TOK) * (g_prob[e] / (float)T_TOK);
        out[OFF_AUX] = (float)NEXP * aux;
        out[OFF_Z]   = g_zsum / (float)T_TOK;
    }
}

// ---------------------------------------------------------------------------
#define SMEM_GATEUP (3 * (128 * LDAK + 2 * 32 * LDB) * 4)   // 110592 B
#define SMEM_DOWN   (3 * (128 * LDAK + 32 * LDB2) * 4)      // 107520 B

extern "C" void kernel_launch(void* const* d_in, const int* in_sizes, int n_in,
                              void* d_out, int out_size) {
    const float* x   = (const float*)d_in[0];
    const float* rw  = (const float*)d_in[1];
    const float* gw  = (const float*)d_in[2];
    const float* uw  = (const float*)d_in[3];
    const float* dw  = (const float*)d_in[4];
    const float* sgw = (const float*)d_in[5];
    const float* suw = (const float*)d_in[6];
    const float* sdw = (const float*)d_in[7];
    float* out = (float*)d_out;

    cudaFuncSetAttribute(gateup_mma_kernel,
                         cudaFuncAttributeMaxDynamicSharedMemorySize, SMEM_GATEUP);
    cudaFuncSetAttribute(down_mma_kernel,
                         cudaFuncAttributeMaxDynamicSharedMemorySize, SMEM_DOWN);

    cudaMemsetAsync(out, 0, (size_t)4194304 * sizeof(float), 0);
    zero_misc_kernel<<<1, 32>>>();
    router_kernel<<<T_TOK, 128>>>(x, rw, out);
    offsets_kernel<<<1, 1>>>();

    // One merged cvt pass (4 float4 per thread)
    {
        int nblk = (CVT_TOTAL + 256 * 4 - 1) / (256 * 4);   // 14849
        cvt_all_kernel<<<nblk, 256>>>((const float4*)x,
                                      (const float4*)gw, (const float4*)sgw,
                                      (const float4*)uw, (const float4*)suw,
                                      (const float4*)dw, (const float4*)sdw);
    }

    gateup_mma_kernel<<<dim3(IDIM / 64, T_TOK / 128, NE), 256, SMEM_GATEUP>>>();
    down_mma_kernel<<<dim3(HDIM / 128, T_TOK / 128, NE), 256, SMEM_DOWN>>>(out);
    finalize_kernel<<<1, 32>>>(out);
}